// round 1
// baseline (speedup 1.0000x reference)
#include <cuda_runtime.h>

// Problem constants (match the JAX reference)
#define Bsz 128
#define Hdim 256
#define Wdim 1024
#define N_HOLES 5
#define PROB 1.0f
#define HOLE_MINW (Wdim / 10)              // 102
#define HOLE_MINH (Hdim / 10)              // 25
#define N_TOTAL ((long long)Bsz * Hdim * Wdim)   // 33,554,432

// Scratch accumulator (no cudaMalloc allowed)
__device__ double g_sum;

__global__ void zero_accum_kernel() {
    g_sum = 0.0;
}

// Fused copy (x -> out) + global sum reduction.
__global__ void copy_reduce_kernel(const float4* __restrict__ x,
                                   float4* __restrict__ out,
                                   long long n4) {
    long long i = (long long)blockIdx.x * blockDim.x + threadIdx.x;
    long long stride = (long long)gridDim.x * blockDim.x;
    float s = 0.0f;
    for (; i < n4; i += stride) {
        float4 v = x[i];
        out[i] = v;
        s += (v.x + v.y) + (v.z + v.w);
    }
    // warp reduce
    #pragma unroll
    for (int o = 16; o > 0; o >>= 1)
        s += __shfl_down_sync(0xFFFFFFFFu, s, o);
    __shared__ float ws[8];
    int lane = threadIdx.x & 31;
    int warp = threadIdx.x >> 5;
    if (lane == 0) ws[warp] = s;
    __syncthreads();
    if (threadIdx.x < 8) {
        float v = ws[threadIdx.x];
        #pragma unroll
        for (int o = 4; o > 0; o >>= 1)
            v += __shfl_down_sync(0xFFu, v, o);
        if (threadIdx.x == 0)
            atomicAdd(&g_sum, (double)v);
    }
}

// One hole per blockIdx.x; rows strided over blockIdx.y.
__global__ void fill_holes_kernel(const int* __restrict__ xs,
                                  const int* __restrict__ ys,
                                  const int* __restrict__ xs_w_raw,
                                  const int* __restrict__ ys_h_raw,
                                  const float* __restrict__ act_rand,
                                  float* __restrict__ out) {
    int hole = blockIdx.x;                 // 0 .. B*N_HOLES-1
    int b = hole / N_HOLES;
    // act: hole active iff act_rand < PROB
    if (!(act_rand[hole] < PROB)) return;

    int cw = xs[hole];
    int ch = ys[hole];
    int hw = xs_w_raw[hole] + HOLE_MINW;   // hole width
    int hh = ys_h_raw[hole] + HOLE_MINH;   // hole height

    int x0 = min(max(cw - hw / 2, 0), Wdim - 2);
    int x1 = min(max(cw + hw / 2, 1), Wdim - 1);
    int y0 = min(max(ch - hh / 2, 0), Hdim - 2);
    int y1 = min(max(ch + hh / 2, 1), Hdim - 1);

    float fill = (float)(g_sum * (1.0 / (double)N_TOTAL));

    float* base = out + (size_t)b * Hdim * Wdim;
    for (int h = y0 + blockIdx.y; h <= y1; h += gridDim.y) {
        float* row = base + (size_t)h * Wdim;
        for (int w = x0 + threadIdx.x; w <= x1; w += blockDim.x)
            row[w] = fill;
    }
}

extern "C" void kernel_launch(void* const* d_in, const int* in_sizes, int n_in,
                              void* d_out, int out_size) {
    const float* x        = (const float*)d_in[0];
    const int*   xs       = (const int*)d_in[1];
    const int*   ys       = (const int*)d_in[2];
    const int*   xs_w_raw = (const int*)d_in[3];
    const int*   ys_h_raw = (const int*)d_in[4];
    const float* act_rand = (const float*)d_in[5];
    float* out = (float*)d_out;

    zero_accum_kernel<<<1, 1>>>();

    long long n4 = N_TOTAL / 4;            // 8,388,608 float4
    int threads = 256;
    int blocks = 148 * 8;                  // grid-stride across the chip
    copy_reduce_kernel<<<blocks, threads>>>((const float4*)x, (float4*)out, n4);

    dim3 fgrid(Bsz * N_HOLES, 16);
    fill_holes_kernel<<<fgrid, 256>>>(xs, ys, xs_w_raw, ys_h_raw, act_rand, out);
}